// round 1
// baseline (speedup 1.0000x reference)
#include <cuda_runtime.h>
#include <cuda_bf16.h>

// ---------------- problem constants ----------------
#define NN   50000
#define EE   800000
#define HIDD 128
#define OUTD 64
#define NCONV 6

__device__ __constant__ float c_dummy; // keep nvcc happy about empty constant use

constexpr float ALPHA  = 0.1f;
// BETA = log(0.5/9 + 1) = log(19/18)
constexpr float BETA   = 0.05406722127027574f;

// ---------------- device scratch (static, allocation-free) ----------------
__device__ float g_h   [NN * HIDD];   // current hidden state
__device__ float g_x0  [NN * HIDD];   // initial hidden (residual source)
__device__ float g_z   [NN * HIDD];   // pre-GEMM combined state
__device__ int   g_deg [NN];
__device__ int   g_rowptr[NN + 1];
__device__ int   g_cursor[NN];
__device__ int   g_csr_src[EE];
__device__ float g_csr_w  [EE];

// ---------------- CSR build ----------------
__global__ void zero_deg_kernel() {
    int i = blockIdx.x * blockDim.x + threadIdx.x;
    if (i < NN) g_deg[i] = 0;
}

__global__ void hist_kernel(const int* __restrict__ edge_dst) {
    int e = blockIdx.x * blockDim.x + threadIdx.x;
    if (e < EE) atomicAdd(&g_deg[edge_dst[e]], 1);
}

// single-block exclusive scan over g_deg -> g_rowptr, g_cursor
__global__ void scan_kernel() {
    __shared__ int s[1024];
    const int t  = threadIdx.x;
    const int CH = (NN + 1023) / 1024;           // 49
    int start = t * CH;
    int end   = start + CH; if (end > NN) end = NN;
    int sum = 0;
    for (int i = start; i < end; i++) sum += g_deg[i];
    s[t] = sum;
    __syncthreads();
    if (t == 0) {
        int run = 0;
        for (int i = 0; i < 1024; i++) { int v = s[i]; s[i] = run; run += v; }
        g_rowptr[NN] = run;                       // == EE
    }
    __syncthreads();
    int run = s[t];
    for (int i = start; i < end; i++) {
        g_rowptr[i] = run;
        g_cursor[i] = run;
        run += g_deg[i];
    }
}

__global__ void fill_kernel(const int* __restrict__ edge_src,
                            const int* __restrict__ edge_dst,
                            const float* __restrict__ edge_w) {
    int e = blockIdx.x * blockDim.x + threadIdx.x;
    if (e < EE) {
        int d    = edge_dst[e];
        int slot = atomicAdd(&g_cursor[d], 1);
        g_csr_src[slot] = edge_src[e];
        g_csr_w  [slot] = edge_w[e];
    }
}

// ---------------- aggregation + residual combine ----------------
// one block per node; 128 threads = feature lanes
// z[n] = (1-ALPHA) * sum_e w_e * h[src_e] + ALPHA * x0[n]
__global__ void __launch_bounds__(128) agg_kernel() {
    const int n = blockIdx.x;
    const int c = threadIdx.x;
    __shared__ int   ss[128];
    __shared__ float sw[128];

    int beg = g_rowptr[n];
    int end = g_rowptr[n + 1];
    float acc = 0.0f;
    for (int base = beg; base < end; base += 128) {
        int cnt = end - base; if (cnt > 128) cnt = 128;
        if (c < cnt) { ss[c] = g_csr_src[base + c]; sw[c] = g_csr_w[base + c]; }
        __syncthreads();
        for (int i = 0; i < cnt; i++) {
            acc += sw[i] * g_h[ss[i] * HIDD + c];
        }
        __syncthreads();
    }
    g_z[n * HIDD + c] = (1.0f - ALPHA) * acc + ALPHA * g_x0[n * HIDD + c];
}

// ---------------- fused fp32 GEMM ----------------
// C[M, NC] = A[M,128] @ B[128, NC]  with fused epilogue
// MODE 0: out  = relu(acc + bias);  out2 = same (h and x0)
// MODE 1: out  = relu((1-BETA)*A[r][c] + BETA*acc)      (A == z)
// MODE 2: out  = acc + bias
// TM=64 rows/block, K processed in two KT=64 passes. 48KB static smem.
template<int NC, int MODE>
__global__ void __launch_bounds__(256) gemm_kernel(const float* __restrict__ A,
                                                   const float* __restrict__ B,
                                                   const float* __restrict__ bias,
                                                   float* __restrict__ out,
                                                   float* __restrict__ out2) {
    constexpr int TM = 64;
    constexpr int KT = 64;
    constexpr int G  = NC / 4;          // float4 column groups (32 or 16)
    constexpr int RT = TM * G / 256;    // rows per thread (8 or 4)

    __shared__ float Ws[KT * NC];       // 32KB (NC=128) / 16KB (NC=64)
    __shared__ float Zs[TM * KT];       // 16KB

    const int tid  = threadIdx.x;
    const int row0 = blockIdx.x * TM;
    const int tx   = tid % G;
    const int ty   = tid / G;

    float acc[RT][4];
#pragma unroll
    for (int i = 0; i < RT; i++) { acc[i][0]=0.f; acc[i][1]=0.f; acc[i][2]=0.f; acc[i][3]=0.f; }

    for (int kt = 0; kt < 128; kt += KT) {
        // ---- load W k-slice [KT x NC]
        {
            const float4* Bv = (const float4*)(B + kt * NC);
            float4* Wv = (float4*)Ws;
#pragma unroll
            for (int i = tid; i < KT * NC / 4; i += 256) Wv[i] = Bv[i];
        }
        // ---- load A tile [TM x KT]
        {
            float4* Zv = (float4*)Zs;
#pragma unroll
            for (int i = tid; i < TM * KT / 4; i += 256) {
                int r  = i / (KT / 4);
                int cc = i % (KT / 4);
                int gr = row0 + r;
                float4 v;
                if (gr < NN) v = *(const float4*)(A + gr * 128 + kt + cc * 4);
                else         v = make_float4(0.f, 0.f, 0.f, 0.f);
                Zv[i] = v;
            }
        }
        __syncthreads();

#pragma unroll 8
        for (int k = 0; k < KT; k++) {
            float4 w = ((const float4*)Ws)[k * G + tx];
#pragma unroll
            for (int i = 0; i < RT; i++) {
                float zv = Zs[(ty * RT + i) * KT + k];
                acc[i][0] += zv * w.x;
                acc[i][1] += zv * w.y;
                acc[i][2] += zv * w.z;
                acc[i][3] += zv * w.w;
            }
        }
        __syncthreads();
    }

    // ---- epilogue
    const int col = tx * 4;
#pragma unroll
    for (int i = 0; i < RT; i++) {
        int row = row0 + ty * RT + i;
        if (row >= NN) continue;
        float4 v;
        if (MODE == 0) {
            float4 b = *(const float4*)(bias + col);
            v.x = fmaxf(acc[i][0] + b.x, 0.f);
            v.y = fmaxf(acc[i][1] + b.y, 0.f);
            v.z = fmaxf(acc[i][2] + b.z, 0.f);
            v.w = fmaxf(acc[i][3] + b.w, 0.f);
            *(float4*)(out  + row * NC + col) = v;
            *(float4*)(out2 + row * NC + col) = v;
        } else if (MODE == 1) {
            float4 z = *(const float4*)(A + row * 128 + col);  // L2 hit
            v.x = fmaxf((1.f - BETA) * z.x + BETA * acc[i][0], 0.f);
            v.y = fmaxf((1.f - BETA) * z.y + BETA * acc[i][1], 0.f);
            v.z = fmaxf((1.f - BETA) * z.z + BETA * acc[i][2], 0.f);
            v.w = fmaxf((1.f - BETA) * z.w + BETA * acc[i][3], 0.f);
            *(float4*)(out + row * NC + col) = v;
        } else {
            float4 b = *(const float4*)(bias + col);
            v.x = acc[i][0] + b.x;
            v.y = acc[i][1] + b.y;
            v.z = acc[i][2] + b.z;
            v.w = acc[i][3] + b.w;
            *(float4*)(out + row * NC + col) = v;
        }
    }
}

// ---------------- launch ----------------
extern "C" void kernel_launch(void* const* d_in, const int* in_sizes, int n_in,
                              void* d_out, int out_size) {
    const float* x        = (const float*)d_in[0];
    const int*   edge_src = (const int*)  d_in[1];
    const int*   edge_dst = (const int*)  d_in[2];
    const float* edge_w   = (const float*)d_in[3];
    const float* W0       = (const float*)d_in[4];
    const float* b0       = (const float*)d_in[5];
    const float* W1       = (const float*)d_in[6];
    const float* b1       = (const float*)d_in[7];
    const float* conv_ws  = (const float*)d_in[8];
    float* outp = (float*)d_out;

    float* g_h_p;   cudaGetSymbolAddress((void**)&g_h_p,  g_h);
    float* g_x0_p;  cudaGetSymbolAddress((void**)&g_x0_p, g_x0);
    float* g_z_p;   cudaGetSymbolAddress((void**)&g_z_p,  g_z);

    // ---- CSR build (per launch; deterministic workload)
    zero_deg_kernel<<<(NN + 255) / 256, 256>>>();
    hist_kernel<<<(EE + 255) / 256, 256>>>(edge_dst);
    scan_kernel<<<1, 1024>>>();
    fill_kernel<<<(EE + 255) / 256, 256>>>(edge_src, edge_dst, edge_w);

    const int gemm_grid = (NN + 63) / 64;

    // ---- first layer: h = x0 = relu(x @ W0 + b0)
    gemm_kernel<HIDD, 0><<<gemm_grid, 256>>>(x, W0, b0, g_h_p, g_x0_p);

    // ---- 6 GCN2 conv layers
    for (int i = 0; i < NCONV; i++) {
        agg_kernel<<<NN, 128>>>();
        gemm_kernel<HIDD, 1><<<gemm_grid, 256>>>(g_z_p, conv_ws + i * HIDD * HIDD,
                                                 nullptr, g_h_p, nullptr);
    }

    // ---- final: out = h @ W1 + b1
    gemm_kernel<OUTD, 2><<<gemm_grid, 256>>>(g_h_p, W1, b1, outp, nullptr);
}

// round 5
// speedup vs baseline: 1.0497x; 1.0497x over previous
#include <cuda_runtime.h>
#include <cuda_bf16.h>
#include <cstdint>

// ---------------- problem constants ----------------
#define NN   50000
#define EE   800000
#define HIDD 128
#define OUTD 64
#define NCONV 6

constexpr float ALPHA  = 0.1f;
// BETA = log(0.5/9 + 1)
constexpr float BETA   = 0.05406722127027574f;

// ---------------- device scratch (static, allocation-free) ----------------
__device__ float g_h   [NN * HIDD];
__device__ float g_x0  [NN * HIDD];
__device__ float g_z   [NN * HIDD];
__device__ int   g_deg [NN];
__device__ int   g_rowptr[NN + 1];
__device__ int   g_cursor[NN];
__device__ int   g_csr_src[EE];
__device__ float g_csr_w  [EE];
// weights, transposed to [n][k], bf16 hi/lo split: 7 mats 128x128 + 1 mat 64x128
__device__ __nv_bfloat16 g_wb_hi[7 * 16384 + 64 * 128];
__device__ __nv_bfloat16 g_wb_lo[7 * 16384 + 64 * 128];

// ---------------- helpers ----------------
__device__ __forceinline__ uint32_t smem_u32(const void* p) {
    uint32_t a;
    asm("{ .reg .u64 t; cvta.to.shared.u64 t, %1; cvt.u32.u64 %0, t; }" : "=r"(a) : "l"(p));
    return a;
}
__device__ __forceinline__ void ldsm_x4(uint32_t* r, uint32_t addr) {
    asm volatile("ldmatrix.sync.aligned.m8n8.x4.shared.b16 {%0,%1,%2,%3}, [%4];"
                 : "=r"(r[0]), "=r"(r[1]), "=r"(r[2]), "=r"(r[3]) : "r"(addr));
}
__device__ __forceinline__ void mma_bf16(float* c, const uint32_t* a, uint32_t b0, uint32_t b1) {
    asm volatile("mma.sync.aligned.m16n8k16.row.col.f32.bf16.bf16.f32 "
                 "{%0,%1,%2,%3}, {%4,%5,%6,%7}, {%8,%9}, {%0,%1,%2,%3};"
                 : "+f"(c[0]), "+f"(c[1]), "+f"(c[2]), "+f"(c[3])
                 : "r"(a[0]), "r"(a[1]), "r"(a[2]), "r"(a[3]), "r"(b0), "r"(b1));
}
__device__ __forceinline__ uint32_t pack_bf2(__nv_bfloat16 a, __nv_bfloat16 b) {
    __nv_bfloat162 t(a, b);
    return *reinterpret_cast<uint32_t*>(&t);
}

// ---------------- CSR build ----------------
__global__ void zero_deg_kernel() {
    int i = blockIdx.x * blockDim.x + threadIdx.x;
    if (i < NN) g_deg[i] = 0;
}
__global__ void hist_kernel(const int* __restrict__ edge_dst) {
    int e = blockIdx.x * blockDim.x + threadIdx.x;
    if (e < EE) atomicAdd(&g_deg[edge_dst[e]], 1);
}
__global__ void scan_kernel() {
    __shared__ int s[1024];
    const int t  = threadIdx.x;
    const int CH = (NN + 1023) / 1024;
    int start = t * CH;
    int end   = start + CH; if (end > NN) end = NN;
    int sum = 0;
    for (int i = start; i < end; i++) sum += g_deg[i];
    s[t] = sum;
    __syncthreads();
    if (t == 0) {
        int run = 0;
        for (int i = 0; i < 1024; i++) { int v = s[i]; s[i] = run; run += v; }
        g_rowptr[NN] = run;
    }
    __syncthreads();
    int run = s[t];
    for (int i = start; i < end; i++) {
        g_rowptr[i] = run;
        g_cursor[i] = run;
        run += g_deg[i];
    }
}
__global__ void fill_kernel(const int* __restrict__ edge_src,
                            const int* __restrict__ edge_dst,
                            const float* __restrict__ edge_w) {
    int e = blockIdx.x * blockDim.x + threadIdx.x;
    if (e < EE) {
        int d    = edge_dst[e];
        int slot = atomicAdd(&g_cursor[d], 1);
        g_csr_src[slot] = edge_src[e];
        g_csr_w  [slot] = edge_w[e];
    }
}

// ---------------- weight prep: transpose + bf16 hi/lo split ----------------
// layout: g_wb[m*16384 + n*128 + k] = W_m[k][n]   (m=0: W0; m=1..6: conv; m=7: W1, n<64)
__global__ void prep_weights(const float* __restrict__ W0,
                             const float* __restrict__ conv_ws,
                             const float* __restrict__ W1) {
    int i = blockIdx.x * blockDim.x + threadIdx.x;
    const int TOT = 7 * 16384 + 64 * 128;
    if (i >= TOT) return;
    float v;
    int dst;
    if (i < 7 * 16384) {
        int m = i / 16384, r = i % 16384;
        int n = r / 128, k = r % 128;
        v = (m == 0) ? W0[k * 128 + n] : conv_ws[(m - 1) * 16384 + k * 128 + n];
        dst = m * 16384 + n * 128 + k;
    } else {
        int r = i - 7 * 16384;
        int n = r / 128, k = r % 128;
        v = W1[k * 64 + n];
        dst = 7 * 16384 + n * 128 + k;
    }
    __nv_bfloat16 hi = __float2bfloat16(v);
    float lo = v - __bfloat162float(hi);
    g_wb_hi[dst] = hi;
    g_wb_lo[dst] = __float2bfloat16(lo);
}

// ---------------- aggregation + residual combine ----------------
__global__ void __launch_bounds__(128) agg_kernel() {
    const int n = blockIdx.x;
    const int c = threadIdx.x;
    __shared__ int   ss[128];
    __shared__ float sw[128];
    int beg = g_rowptr[n];
    int end = g_rowptr[n + 1];
    float acc = 0.0f;
    for (int base = beg; base < end; base += 128) {
        int cnt = end - base; if (cnt > 128) cnt = 128;
        if (c < cnt) { ss[c] = g_csr_src[base + c]; sw[c] = g_csr_w[base + c]; }
        __syncthreads();
        for (int i = 0; i < cnt; i++) {
            acc += sw[i] * g_h[ss[i] * HIDD + c];
        }
        __syncthreads();
    }
    g_z[n * HIDD + c] = (1.0f - ALPHA) * acc + ALPHA * g_x0[n * HIDD + c];
}

// ---------------- mma.sync bf16 hi/lo GEMM: C[M,NC] = A[M,128] @ W ----------------
// MODE 0: out = relu(acc + bias), also written to out2
// MODE 1: out = relu((1-BETA)*A + BETA*acc)
// MODE 2: out = acc + bias
// CTA: 256 threads (8 warps), 128 rows. Warp w owns rows w*16..w*16+15, all NC cols.
// K in two 64-chunks; smem tiles padded to 72-element stride (conflict-free ldmatrix).
template<int NC, int MODE>
__global__ void __launch_bounds__(256) mma_gemm(const float* __restrict__ A,
                                                const __nv_bfloat16* __restrict__ Bhi_g,
                                                const __nv_bfloat16* __restrict__ Blo_g,
                                                const float* __restrict__ bias,
                                                float* __restrict__ out,
                                                float* __restrict__ out2) {
    constexpr int AST = 72;            // smem row stride (bf16 elements)
    constexpr int NT8 = NC / 8;        // n8 tiles per warp (16 or 8)
    extern __shared__ char smem[];
    __nv_bfloat16* sAhi = (__nv_bfloat16*)smem;          // [128][72]
    __nv_bfloat16* sAlo = sAhi + 128 * AST;
    __nv_bfloat16* sBhi = sAlo + 128 * AST;              // [NC][72]
    __nv_bfloat16* sBlo = sBhi + NC * AST;

    const int tid  = threadIdx.x;
    const int warp = tid >> 5;
    const int lane = tid & 31;
    const int row0 = blockIdx.x * 128;

    float acc[NT8][4];
#pragma unroll
    for (int g = 0; g < NT8; g++) {
        acc[g][0] = 0.f; acc[g][1] = 0.f; acc[g][2] = 0.f; acc[g][3] = 0.f;
    }

    // precompute ldmatrix lane addressing pieces
    const int a_row  = warp * 16 + (lane & 15);
    const int a_koff = (lane >> 4) * 8;                  // element offset (16B half)
    const int b_rsub = ((lane >> 3) & 1) * 8 + (lane & 7);
    const int b_koff = (lane >> 4) * 8;

    for (int kc = 0; kc < 2; kc++) {
        // ---- stage A chunk: 128 rows x 64 k, fp32 -> bf16 hi/lo
        for (int i = tid; i < 128 * 16; i += 256) {      // 16 float4 per row
            int r  = i >> 4;
            int c4 = (i & 15) << 2;
            int gr = row0 + r;
            float4 v = make_float4(0.f, 0.f, 0.f, 0.f);
            if (gr < NN) v = *(const float4*)(A + gr * 128 + kc * 64 + c4);
            __nv_bfloat16 h0 = __float2bfloat16(v.x), h1 = __float2bfloat16(v.y);
            __nv_bfloat16 h2 = __float2bfloat16(v.z), h3 = __float2bfloat16(v.w);
            float l0 = v.x - __bfloat162float(h0);
            float l1 = v.y - __bfloat162float(h1);
            float l2 = v.z - __bfloat162float(h2);
            float l3 = v.w - __bfloat162float(h3);
            uint2 hv = make_uint2(pack_bf2(h0, h1), pack_bf2(h2, h3));
            uint2 lv = make_uint2(pack_bf2(__float2bfloat16(l0), __float2bfloat16(l1)),
                                  pack_bf2(__float2bfloat16(l2), __float2bfloat16(l3)));
            *(uint2*)(sAhi + r * AST + c4) = hv;
            *(uint2*)(sAlo + r * AST + c4) = lv;
        }
        // ---- stage B chunk: NC rows x 64 k (already bf16 [n][k])
        for (int i = tid; i < NC * 8; i += 256) {        // 8 x uint4 (8 bf16) per row
            int r = i >> 3;
            int c = (i & 7) << 3;
            *(uint4*)(sBhi + r * AST + c) = *(const uint4*)(Bhi_g + r * 128 + kc * 64 + c);
            *(uint4*)(sBlo + r * AST + c) = *(const uint4*)(Blo_g + r * 128 + kc * 64 + c);
        }
        __syncthreads();

#pragma unroll
        for (int ks = 0; ks < 4; ks++) {
            uint32_t ah[4], al[4];
            uint32_t aaddr = smem_u32(sAhi + a_row * AST + ks * 16 + a_koff);
            ldsm_x4(ah, aaddr);
            ldsm_x4(al, aaddr + 2 * 128 * AST);          // sAlo at fixed byte offset
#pragma unroll
            for (int g = 0; g < NT8 / 2; g++) {
                uint32_t bh[4], bl[4];
                uint32_t baddr = smem_u32(sBhi + (g * 16 + b_rsub) * AST + ks * 16 + b_koff);
                ldsm_x4(bh, baddr);
                ldsm_x4(bl, baddr + 2 * NC * AST);       // sBlo at fixed byte offset
                // tile 2g   : rows n0-7  -> frags {bh[0], bh[2]}
                // tile 2g+1 : rows n8-15 -> frags {bh[1], bh[3]}
                mma_bf16(acc[2 * g],     ah, bh[0], bh[2]);
                mma_bf16(acc[2 * g],     ah, bl[0], bl[2]);
                mma_bf16(acc[2 * g],     al, bh[0], bh[2]);
                mma_bf16(acc[2 * g + 1], ah, bh[1], bh[3]);
                mma_bf16(acc[2 * g + 1], ah, bl[1], bl[3]);
                mma_bf16(acc[2 * g + 1], al, bh[1], bh[3]);
            }
        }
        __syncthreads();
    }

    // ---- epilogue: thread holds D[r][c],D[r][c+1] (acc[g][0..1]) and D[r+8][c..c+1] (acc[g][2..3])
    const int r_lo = row0 + warp * 16 + (lane >> 2);
    const int cb   = (lane & 3) * 2;
#pragma unroll
    for (int g = 0; g < NT8; g++) {
        int col = g * 8 + cb;
#pragma unroll
        for (int half = 0; half < 2; half++) {
            int row = r_lo + half * 8;
            if (row >= NN) continue;
            float a0 = acc[g][half * 2];
            float a1 = acc[g][half * 2 + 1];
            float2 o;
            if (MODE == 0) {
                float2 b = *(const float2*)(bias + col);
                o.x = fmaxf(a0 + b.x, 0.f);
                o.y = fmaxf(a1 + b.y, 0.f);
                *(float2*)(out  + row * NC + col) = o;
                *(float2*)(out2 + row * NC + col) = o;
            } else if (MODE == 1) {
                float2 z = *(const float2*)(A + row * 128 + col);
                o.x = fmaxf((1.f - BETA) * z.x + BETA * a0, 0.f);
                o.y = fmaxf((1.f - BETA) * z.y + BETA * a1, 0.f);
                *(float2*)(out + row * NC + col) = o;
            } else {
                float2 b = *(const float2*)(bias + col);
                o.x = a0 + b.x;
                o.y = a1 + b.y;
                *(float2*)(out + row * NC + col) = o;
            }
        }
    }
}

// ---------------- launch ----------------
extern "C" void kernel_launch(void* const* d_in, const int* in_sizes, int n_in,
                              void* d_out, int out_size) {
    const float* x        = (const float*)d_in[0];
    const int*   edge_src = (const int*)  d_in[1];
    const int*   edge_dst = (const int*)  d_in[2];
    const float* edge_w   = (const float*)d_in[3];
    const float* W0       = (const float*)d_in[4];
    const float* b0       = (const float*)d_in[5];
    const float* W1       = (const float*)d_in[6];
    const float* b1       = (const float*)d_in[7];
    const float* conv_ws  = (const float*)d_in[8];
    float* outp = (float*)d_out;

    float* g_h_p;   cudaGetSymbolAddress((void**)&g_h_p,  g_h);
    float* g_x0_p;  cudaGetSymbolAddress((void**)&g_x0_p, g_x0);
    float* g_z_p;   cudaGetSymbolAddress((void**)&g_z_p,  g_z);
    __nv_bfloat16* wbh; cudaGetSymbolAddress((void**)&wbh, g_wb_hi);
    __nv_bfloat16* wbl; cudaGetSymbolAddress((void**)&wbl, g_wb_lo);

    // dynamic smem: (2*128 + 2*NC) * 72 * 2 bytes
    const int SMEM_128 = (2 * 128 + 2 * 128) * 72 * 2;   // 73728
    const int SMEM_64  = (2 * 128 + 2 * 64)  * 72 * 2;   // 55296
    cudaFuncSetAttribute(mma_gemm<HIDD, 0>, cudaFuncAttributeMaxDynamicSharedMemorySize, SMEM_128);
    cudaFuncSetAttribute(mma_gemm<HIDD, 1>, cudaFuncAttributeMaxDynamicSharedMemorySize, SMEM_128);
    cudaFuncSetAttribute(mma_gemm<OUTD, 2>, cudaFuncAttributeMaxDynamicSharedMemorySize, SMEM_64);

    // ---- CSR build
    zero_deg_kernel<<<(NN + 255) / 256, 256>>>();
    hist_kernel<<<(EE + 255) / 256, 256>>>(edge_dst);
    scan_kernel<<<1, 1024>>>();
    fill_kernel<<<(EE + 255) / 256, 256>>>(edge_src, edge_dst, edge_w);

    // ---- weight prep (transpose + hi/lo split)
    prep_weights<<<(7 * 16384 + 64 * 128 + 255) / 256, 256>>>(W0, conv_ws, W1);

    const int gemm_grid = (NN + 127) / 128;   // 391

    // ---- first layer: h = x0 = relu(x @ W0 + b0)
    mma_gemm<HIDD, 0><<<gemm_grid, 256, SMEM_128>>>(x, wbh, wbl, b0, g_h_p, g_x0_p);

    // ---- 6 GCN2 conv layers
    for (int i = 0; i < NCONV; i++) {
        agg_kernel<<<NN, 128>>>();
        mma_gemm<HIDD, 1><<<gemm_grid, 256, SMEM_128>>>(g_z_p,
                                                        wbh + (1 + i) * 16384,
                                                        wbl + (1 + i) * 16384,
                                                        nullptr, g_h_p, nullptr);
    }

    // ---- final: out = h @ W1 + b1
    mma_gemm<OUTD, 2><<<gemm_grid, 256, SMEM_64>>>(g_h_p, wbh + 7 * 16384, wbl + 7 * 16384,
                                                   b1, outp, nullptr);
}

// round 7
// speedup vs baseline: 1.2025x; 1.1456x over previous
#include <cuda_runtime.h>
#include <cuda_bf16.h>
#include <cstdint>

// ---------------- problem constants ----------------
#define NN   50000
#define EE   800000
#define HIDD 128
#define OUTD 64
#define NCONV 6

constexpr float ALPHA  = 0.1f;
// BETA = log(0.5/9 + 1)
constexpr float BETA   = 0.05406722127027574f;

// ---------------- device scratch (static, allocation-free) ----------------
__device__ float g_h   [NN * HIDD];
__device__ float g_x0  [NN * HIDD];
__device__ float g_z   [NN * HIDD];
__device__ int   g_deg [NN];
__device__ int   g_rowptr[NN + 1];
__device__ int   g_cursor[NN];
__device__ int   g_csr_src[EE];
__device__ float g_csr_w  [EE];
// weights, transposed to [n][k], bf16 hi/lo split: 7 mats 128x128 + 1 mat 64x128
__device__ __nv_bfloat16 g_wb_hi[7 * 16384 + 64 * 128];
__device__ __nv_bfloat16 g_wb_lo[7 * 16384 + 64 * 128];

// ---------------- helpers ----------------
__device__ __forceinline__ uint32_t smem_u32(const void* p) {
    uint32_t a;
    asm("{ .reg .u64 t; cvta.to.shared.u64 t, %1; cvt.u32.u64 %0, t; }" : "=r"(a) : "l"(p));
    return a;
}
__device__ __forceinline__ void ldsm_x4(uint32_t* r, uint32_t addr) {
    asm volatile("ldmatrix.sync.aligned.m8n8.x4.shared.b16 {%0,%1,%2,%3}, [%4];"
                 : "=r"(r[0]), "=r"(r[1]), "=r"(r[2]), "=r"(r[3]) : "r"(addr));
}
__device__ __forceinline__ void mma_bf16(float* c, const uint32_t* a, uint32_t b0, uint32_t b1) {
    asm volatile("mma.sync.aligned.m16n8k16.row.col.f32.bf16.bf16.f32 "
                 "{%0,%1,%2,%3}, {%4,%5,%6,%7}, {%8,%9}, {%0,%1,%2,%3};"
                 : "+f"(c[0]), "+f"(c[1]), "+f"(c[2]), "+f"(c[3])
                 : "r"(a[0]), "r"(a[1]), "r"(a[2]), "r"(a[3]), "r"(b0), "r"(b1));
}
__device__ __forceinline__ uint32_t pack_bf2(__nv_bfloat16 a, __nv_bfloat16 b) {
    __nv_bfloat162 t(a, b);
    return *reinterpret_cast<uint32_t*>(&t);
}

// ---------------- CSR build ----------------
__global__ void zero_deg_kernel() {
    int i = blockIdx.x * blockDim.x + threadIdx.x;
    if (i < NN) g_deg[i] = 0;
}
__global__ void hist_kernel(const int* __restrict__ edge_dst) {
    int e = blockIdx.x * blockDim.x + threadIdx.x;
    if (e < EE) atomicAdd(&g_deg[edge_dst[e]], 1);
}
__global__ void scan_kernel() {
    __shared__ int s[1024];
    const int t  = threadIdx.x;
    const int CH = (NN + 1023) / 1024;
    int start = t * CH;
    int end   = start + CH; if (end > NN) end = NN;
    int sum = 0;
    for (int i = start; i < end; i++) sum += g_deg[i];
    s[t] = sum;
    __syncthreads();
    if (t == 0) {
        int run = 0;
        for (int i = 0; i < 1024; i++) { int v = s[i]; s[i] = run; run += v; }
        g_rowptr[NN] = run;
    }
    __syncthreads();
    int run = s[t];
    for (int i = start; i < end; i++) {
        g_rowptr[i] = run;
        g_cursor[i] = run;
        run += g_deg[i];
    }
}
__global__ void fill_kernel(const int* __restrict__ edge_src,
                            const int* __restrict__ edge_dst,
                            const float* __restrict__ edge_w) {
    int e = blockIdx.x * blockDim.x + threadIdx.x;
    if (e < EE) {
        int d    = edge_dst[e];
        int slot = atomicAdd(&g_cursor[d], 1);
        g_csr_src[slot] = edge_src[e];
        g_csr_w  [slot] = edge_w[e];
    }
}

// ---------------- weight prep: transpose + bf16 hi/lo split ----------------
__global__ void prep_weights(const float* __restrict__ W0,
                             const float* __restrict__ conv_ws,
                             const float* __restrict__ W1) {
    int i = blockIdx.x * blockDim.x + threadIdx.x;
    const int TOT = 7 * 16384 + 64 * 128;
    if (i >= TOT) return;
    float v;
    int dst;
    if (i < 7 * 16384) {
        int m = i / 16384, r = i % 16384;
        int n = r / 128, k = r % 128;
        v = (m == 0) ? W0[k * 128 + n] : conv_ws[(m - 1) * 16384 + k * 128 + n];
        dst = m * 16384 + n * 128 + k;
    } else {
        int r = i - 7 * 16384;
        int n = r / 128, k = r % 128;
        v = W1[k * 64 + n];
        dst = 7 * 16384 + n * 128 + k;
    }
    __nv_bfloat16 hi = __float2bfloat16(v);
    float lo = v - __bfloat162float(hi);
    g_wb_hi[dst] = hi;
    g_wb_lo[dst] = __float2bfloat16(lo);
}

// ---------------- aggregation: warp-per-node, float4 lanes, shfl edge broadcast ----------------
// z[n] = (1-ALPHA) * sum_e w_e * h[src_e] + ALPHA * x0[n]
// lane owns features [lane*4, lane*4+4). 4 accumulators -> 4 outstanding LDG.128.
__global__ void __launch_bounds__(256) agg_kernel() {
    const int warp = threadIdx.x >> 5;
    const int lane = threadIdx.x & 31;
    const int n    = blockIdx.x * 8 + warp;
    if (n >= NN) return;

    const int beg = g_rowptr[n];
    const int end = g_rowptr[n + 1];
    const int c4  = lane * 4;

    float4 a0 = make_float4(0.f, 0.f, 0.f, 0.f);
    float4 a1 = a0, a2 = a0, a3 = a0;

    for (int base = beg; base < end; base += 32) {
        int cnt = end - base; if (cnt > 32) cnt = 32;
        int   src = 0;
        float wt  = 0.f;
        if (lane < cnt) {
            src = g_csr_src[base + lane];
            wt  = g_csr_w  [base + lane];
        }
        int j = 0;
        for (; j + 4 <= cnt; j += 4) {
            int   s0 = __shfl_sync(0xFFFFFFFFu, src, j);
            int   s1 = __shfl_sync(0xFFFFFFFFu, src, j + 1);
            int   s2 = __shfl_sync(0xFFFFFFFFu, src, j + 2);
            int   s3 = __shfl_sync(0xFFFFFFFFu, src, j + 3);
            float w0 = __shfl_sync(0xFFFFFFFFu, wt,  j);
            float w1 = __shfl_sync(0xFFFFFFFFu, wt,  j + 1);
            float w2 = __shfl_sync(0xFFFFFFFFu, wt,  j + 2);
            float w3 = __shfl_sync(0xFFFFFFFFu, wt,  j + 3);
            float4 r0 = *(const float4*)(g_h + s0 * HIDD + c4);
            float4 r1 = *(const float4*)(g_h + s1 * HIDD + c4);
            float4 r2 = *(const float4*)(g_h + s2 * HIDD + c4);
            float4 r3 = *(const float4*)(g_h + s3 * HIDD + c4);
            a0.x += w0 * r0.x; a0.y += w0 * r0.y; a0.z += w0 * r0.z; a0.w += w0 * r0.w;
            a1.x += w1 * r1.x; a1.y += w1 * r1.y; a1.z += w1 * r1.z; a1.w += w1 * r1.w;
            a2.x += w2 * r2.x; a2.y += w2 * r2.y; a2.z += w2 * r2.z; a2.w += w2 * r2.w;
            a3.x += w3 * r3.x; a3.y += w3 * r3.y; a3.z += w3 * r3.z; a3.w += w3 * r3.w;
        }
        for (; j < cnt; j++) {
            int   s = __shfl_sync(0xFFFFFFFFu, src, j);
            float w = __shfl_sync(0xFFFFFFFFu, wt,  j);
            float4 r = *(const float4*)(g_h + s * HIDD + c4);
            a0.x += w * r.x; a0.y += w * r.y; a0.z += w * r.z; a0.w += w * r.w;
        }
    }

    float4 acc;
    acc.x = (a0.x + a1.x) + (a2.x + a3.x);
    acc.y = (a0.y + a1.y) + (a2.y + a3.y);
    acc.z = (a0.z + a1.z) + (a2.z + a3.z);
    acc.w = (a0.w + a1.w) + (a2.w + a3.w);

    float4 x0v = *(const float4*)(g_x0 + n * HIDD + c4);
    float4 z;
    z.x = (1.0f - ALPHA) * acc.x + ALPHA * x0v.x;
    z.y = (1.0f - ALPHA) * acc.y + ALPHA * x0v.y;
    z.z = (1.0f - ALPHA) * acc.z + ALPHA * x0v.z;
    z.w = (1.0f - ALPHA) * acc.w + ALPHA * x0v.w;
    *(float4*)(g_z + n * HIDD + c4) = z;
}

// ---------------- mma.sync bf16 hi/lo GEMM: C[M,NC] = A[M,128] @ W ----------------
// MODE 0: out = relu(acc + bias), also written to out2
// MODE 1: out = relu((1-BETA)*A + BETA*acc)
// MODE 2: out = acc + bias
template<int NC, int MODE>
__global__ void __launch_bounds__(256) mma_gemm(const float* __restrict__ A,
                                                const __nv_bfloat16* __restrict__ Bhi_g,
                                                const __nv_bfloat16* __restrict__ Blo_g,
                                                const float* __restrict__ bias,
                                                float* __restrict__ out,
                                                float* __restrict__ out2) {
    constexpr int AST = 72;            // smem row stride (bf16 elements)
    constexpr int NT8 = NC / 8;        // n8 tiles per warp (16 or 8)
    extern __shared__ char smem[];
    __nv_bfloat16* sAhi = (__nv_bfloat16*)smem;          // [128][72]
    __nv_bfloat16* sAlo = sAhi + 128 * AST;
    __nv_bfloat16* sBhi = sAlo + 128 * AST;              // [NC][72]
    __nv_bfloat16* sBlo = sBhi + NC * AST;

    const int tid  = threadIdx.x;
    const int warp = tid >> 5;
    const int lane = tid & 31;
    const int row0 = blockIdx.x * 128;

    float acc[NT8][4];
#pragma unroll
    for (int g = 0; g < NT8; g++) {
        acc[g][0] = 0.f; acc[g][1] = 0.f; acc[g][2] = 0.f; acc[g][3] = 0.f;
    }

    const int a_row  = warp * 16 + (lane & 15);
    const int a_koff = (lane >> 4) * 8;
    const int b_rsub = ((lane >> 3) & 1) * 8 + (lane & 7);
    const int b_koff = (lane >> 4) * 8;

    for (int kc = 0; kc < 2; kc++) {
        // ---- stage A chunk: 128 rows x 64 k, fp32 -> bf16 hi/lo
        for (int i = tid; i < 128 * 16; i += 256) {
            int r  = i >> 4;
            int c4 = (i & 15) << 2;
            int gr = row0 + r;
            float4 v = make_float4(0.f, 0.f, 0.f, 0.f);
            if (gr < NN) v = *(const float4*)(A + gr * 128 + kc * 64 + c4);
            __nv_bfloat16 h0 = __float2bfloat16(v.x), h1 = __float2bfloat16(v.y);
            __nv_bfloat16 h2 = __float2bfloat16(v.z), h3 = __float2bfloat16(v.w);
            float l0 = v.x - __bfloat162float(h0);
            float l1 = v.y - __bfloat162float(h1);
            float l2 = v.z - __bfloat162float(h2);
            float l3 = v.w - __bfloat162float(h3);
            uint2 hv = make_uint2(pack_bf2(h0, h1), pack_bf2(h2, h3));
            uint2 lv = make_uint2(pack_bf2(__float2bfloat16(l0), __float2bfloat16(l1)),
                                  pack_bf2(__float2bfloat16(l2), __float2bfloat16(l3)));
            *(uint2*)(sAhi + r * AST + c4) = hv;
            *(uint2*)(sAlo + r * AST + c4) = lv;
        }
        // ---- stage B chunk: NC rows x 64 k (already bf16 [n][k])
        for (int i = tid; i < NC * 8; i += 256) {
            int r = i >> 3;
            int c = (i & 7) << 3;
            *(uint4*)(sBhi + r * AST + c) = *(const uint4*)(Bhi_g + r * 128 + kc * 64 + c);
            *(uint4*)(sBlo + r * AST + c) = *(const uint4*)(Blo_g + r * 128 + kc * 64 + c);
        }
        __syncthreads();

#pragma unroll
        for (int ks = 0; ks < 4; ks++) {
            uint32_t ah[4], al[4];
            uint32_t aaddr = smem_u32(sAhi + a_row * AST + ks * 16 + a_koff);
            ldsm_x4(ah, aaddr);
            ldsm_x4(al, aaddr + 2 * 128 * AST);
#pragma unroll
            for (int g = 0; g < NT8 / 2; g++) {
                uint32_t bh[4], bl[4];
                uint32_t baddr = smem_u32(sBhi + (g * 16 + b_rsub) * AST + ks * 16 + b_koff);
                ldsm_x4(bh, baddr);
                ldsm_x4(bl, baddr + 2 * NC * AST);
                mma_bf16(acc[2 * g],     ah, bh[0], bh[2]);
                mma_bf16(acc[2 * g],     ah, bl[0], bl[2]);
                mma_bf16(acc[2 * g],     al, bh[0], bh[2]);
                mma_bf16(acc[2 * g + 1], ah, bh[1], bh[3]);
                mma_bf16(acc[2 * g + 1], ah, bl[1], bl[3]);
                mma_bf16(acc[2 * g + 1], al, bh[1], bh[3]);
            }
        }
        __syncthreads();
    }

    // ---- epilogue
    const int r_lo = row0 + warp * 16 + (lane >> 2);
    const int cb   = (lane & 3) * 2;
#pragma unroll
    for (int g = 0; g < NT8; g++) {
        int col = g * 8 + cb;
#pragma unroll
        for (int half = 0; half < 2; half++) {
            int row = r_lo + half * 8;
            if (row >= NN) continue;
            float a0 = acc[g][half * 2];
            float a1 = acc[g][half * 2 + 1];
            float2 o;
            if (MODE == 0) {
                float2 b = *(const float2*)(bias + col);
                o.x = fmaxf(a0 + b.x, 0.f);
                o.y = fmaxf(a1 + b.y, 0.f);
                *(float2*)(out  + row * NC + col) = o;
                *(float2*)(out2 + row * NC + col) = o;
            } else if (MODE == 1) {
                float2 z = *(const float2*)(A + row * 128 + col);
                o.x = fmaxf((1.f - BETA) * z.x + BETA * a0, 0.f);
                o.y = fmaxf((1.f - BETA) * z.y + BETA * a1, 0.f);
                *(float2*)(out + row * NC + col) = o;
            } else {
                float2 b = *(const float2*)(bias + col);
                o.x = a0 + b.x;
                o.y = a1 + b.y;
                *(float2*)(out + row * NC + col) = o;
            }
        }
    }
}

// ---------------- launch ----------------
extern "C" void kernel_launch(void* const* d_in, const int* in_sizes, int n_in,
                              void* d_out, int out_size) {
    const float* x        = (const float*)d_in[0];
    const int*   edge_src = (const int*)  d_in[1];
    const int*   edge_dst = (const int*)  d_in[2];
    const float* edge_w   = (const float*)d_in[3];
    const float* W0       = (const float*)d_in[4];
    const float* b0       = (const float*)d_in[5];
    const float* W1       = (const float*)d_in[6];
    const float* b1       = (const float*)d_in[7];
    const float* conv_ws  = (const float*)d_in[8];
    float* outp = (float*)d_out;

    float* g_h_p;   cudaGetSymbolAddress((void**)&g_h_p,  g_h);
    float* g_x0_p;  cudaGetSymbolAddress((void**)&g_x0_p, g_x0);
    float* g_z_p;   cudaGetSymbolAddress((void**)&g_z_p,  g_z);
    __nv_bfloat16* wbh; cudaGetSymbolAddress((void**)&wbh, g_wb_hi);
    __nv_bfloat16* wbl; cudaGetSymbolAddress((void**)&wbl, g_wb_lo);

    const int SMEM_128 = (2 * 128 + 2 * 128) * 72 * 2;   // 73728
    const int SMEM_64  = (2 * 128 + 2 * 64)  * 72 * 2;   // 55296
    cudaFuncSetAttribute(mma_gemm<HIDD, 0>, cudaFuncAttributeMaxDynamicSharedMemorySize, SMEM_128);
    cudaFuncSetAttribute(mma_gemm<HIDD, 1>, cudaFuncAttributeMaxDynamicSharedMemorySize, SMEM_128);
    cudaFuncSetAttribute(mma_gemm<OUTD, 2>, cudaFuncAttributeMaxDynamicSharedMemorySize, SMEM_64);

    // ---- CSR build
    zero_deg_kernel<<<(NN + 255) / 256, 256>>>();
    hist_kernel<<<(EE + 255) / 256, 256>>>(edge_dst);
    scan_kernel<<<1, 1024>>>();
    fill_kernel<<<(EE + 255) / 256, 256>>>(edge_src, edge_dst, edge_w);

    // ---- weight prep (transpose + hi/lo split)
    prep_weights<<<(7 * 16384 + 64 * 128 + 255) / 256, 256>>>(W0, conv_ws, W1);

    const int gemm_grid = (NN + 127) / 128;   // 391
    const int agg_grid  = (NN + 7) / 8;       // 6250

    // ---- first layer: h = x0 = relu(x @ W0 + b0)
    mma_gemm<HIDD, 0><<<gemm_grid, 256, SMEM_128>>>(x, wbh, wbl, b0, g_h_p, g_x0_p);

    // ---- 6 GCN2 conv layers
    for (int i = 0; i < NCONV; i++) {
        agg_kernel<<<agg_grid, 256>>>();
        mma_gemm<HIDD, 1><<<gemm_grid, 256, SMEM_128>>>(g_z_p,
                                                        wbh + (1 + i) * 16384,
                                                        wbl + (1 + i) * 16384,
                                                        nullptr, g_h_p, nullptr);
    }

    // ---- final: out = h @ W1 + b1
    mma_gemm<OUTD, 2><<<gemm_grid, 256, SMEM_64>>>(g_h_p, wbh + 7 * 16384, wbl + 7 * 16384,
                                                   b1, outp, nullptr);
}